// round 16
// baseline (speedup 1.0000x reference)
#include <cuda_runtime.h>
#include <cstdint>

namespace {

constexpr int kB = 16, kC = 64, kH = 128, kW = 128;
constexpr int PX = 68;    // float pitch for weight tiles [64][PX]; 68 % 32 == 4
constexpr int PQ = 36;    // word pitch for bf16x2 Q/K tiles [128][PQ]; 36 % 32 == 4
constexpr int PBW = 68;   // word pitch for bf16x2 E/Ebt/V tiles; 68 % 32 == 4
constexpr int PW = 136;   // float pitch for c-major x tiles [64][PW]; 136 % 32 == 8
constexpr int NTHR = 512;
constexpr int PLANE = kH * kW;

// smem float/word offsets
constexpr int OFF_XL  = 0;                    // [64][PW] fp32
constexpr int OFF_XH  = OFF_XL + 64 * PW;     // 8704
constexpr int OFF_QB  = OFF_XH + 64 * PW;     // 17408: Qb [128][PQ]; V1b aliases
constexpr int OFF_KB  = OFF_QB + 128 * PQ;    // 22016: Kb; V2b aliases
constexpr int OFF_EB  = OFF_KB + 128 * PQ;    // 26624: Eb [128][PBW]
constexpr int OFF_EBT = OFF_EB + 128 * PBW;   // 35328: Ebt [128][PBW]
constexpr int OFF_WB  = OFF_EBT + 128 * PBW;  // 44032: WB  [64][PX] fp32
constexpr int OFF_WB2 = OFF_WB + 64 * PX;     // 48384: WB2 [64][PX] fp32
constexpr int OFF_ROWP= OFF_WB2 + 64 * PX;    // 52736
constexpr int OFF_COLP= OFF_ROWP + 512;       // 53248
constexpr int OFF_STAT= OFF_COLP + 512;       // 53760: meanl,rstdl,meanh,rstdh
constexpr int OFF_T   = OFF_STAT + 512;       // 54272: t1q,t2q,t1k,t2k (64 each)
constexpr int OFF_INV = OFF_T + 256;          // 54528: invrow,invcol
constexpr int SMEM_FLOATS = OFF_INV + 256;    // 54784 -> 219,136 B

__device__ __forceinline__ uint32_t f2t(float x) {
  uint32_t r;
  asm("cvt.rna.tf32.f32 %0, %1;" : "=r"(r) : "f"(x));
  return r;
}
__device__ __forceinline__ float tround(float x) { return __uint_as_float(f2t(x)); }
__device__ __forceinline__ uint32_t fu(float x) { return __float_as_uint(x); }

__device__ __forceinline__ uint32_t bfpack(float lo, float hi) {
  uint32_t r;
  asm("cvt.rn.bf16x2.f32 %0, %1, %2;" : "=r"(r) : "f"(hi), "f"(lo));
  return r;
}

__device__ __forceinline__ void mma8(float* c, uint32_t a0, uint32_t a1, uint32_t a2,
                                     uint32_t a3, uint32_t b0, uint32_t b1) {
  asm volatile(
      "mma.sync.aligned.m16n8k8.row.col.f32.tf32.tf32.f32 "
      "{%0,%1,%2,%3},{%4,%5,%6,%7},{%8,%9},{%0,%1,%2,%3};"
      : "+f"(c[0]), "+f"(c[1]), "+f"(c[2]), "+f"(c[3])
      : "r"(a0), "r"(a1), "r"(a2), "r"(a3), "r"(b0), "r"(b1));
}

__device__ __forceinline__ void mma16(float* c, uint32_t a0, uint32_t a1, uint32_t a2,
                                      uint32_t a3, uint32_t b0, uint32_t b1) {
  asm volatile(
      "mma.sync.aligned.m16n8k16.row.col.f32.bf16.bf16.f32 "
      "{%0,%1,%2,%3},{%4,%5,%6,%7},{%8,%9},{%0,%1,%2,%3};"
      : "+f"(c[0]), "+f"(c[1]), "+f"(c[2]), "+f"(c[3])
      : "r"(a0), "r"(a1), "r"(a2), "r"(a3), "r"(b0), "r"(b1));
}

// 64x64 weight fold (LN gamma) for a 256-thread half; t in [0,256), 4 thr/row.
__device__ __forceinline__ void stage_fold256(
    const float* __restrict__ Wsrc, const float* __restrict__ g,
    const float* __restrict__ bb, float* __restrict__ WB,
    float* __restrict__ t1, float* __restrict__ t2, int t) {
  const int j = t >> 2;
  const int c0 = (t & 3) * 16;
  float s1 = 0.f, s2 = 0.f;
#pragma unroll
  for (int u = 0; u < 16; u++) {
    const int c = c0 + u;
    const float raw = Wsrc[j * 64 + c];
    const float wf = tround(raw * g[c]);
    WB[j * PX + c] = wf;
    s1 += wf;
    s2 += raw * bb[c];
  }
  s1 += __shfl_xor_sync(0xffffffffu, s1, 1);
  s1 += __shfl_xor_sync(0xffffffffu, s1, 2);
  s2 += __shfl_xor_sync(0xffffffffu, s2, 1);
  s2 += __shfl_xor_sync(0xffffffffu, s2, 2);
  if ((t & 3) == 0) { t1[j] = s1; t2[j] = s2; }
}

__device__ __forceinline__ void stage_raw256(
    const float* __restrict__ Wsrc, float* __restrict__ WB, int t) {
  const int j = t >> 2;
  const int c0 = (t & 3) * 16;
#pragma unroll
  for (int u = 0; u < 16; u++) WB[j * PX + c0 + u] = tround(Wsrc[j * 64 + c0 + u]);
}

// Q/K gemm: C = LN(A) @ WB^T -> Qb[w][c/2] bf16 pairs-along-c (local pack).
// A c-major [c][PW]. 16 warps, 4(m)x4(n), 32x16 tiles. (R15-proven.)
__device__ __forceinline__ void gemm_qk(
    const float* __restrict__ A, const float* __restrict__ WB, uint32_t* __restrict__ Qb,
    int wid, int qr, int qc, const float* __restrict__ mean,
    const float* __restrict__ rstd, const float* __restrict__ t1,
    const float* __restrict__ t2) {
  const int r0 = (wid & 3) * 32;
  const int c0 = (wid >> 2) * 16;
  float acc[2][2][4];
#pragma unroll
  for (int mi = 0; mi < 2; mi++)
#pragma unroll
    for (int nj = 0; nj < 2; nj++)
#pragma unroll
      for (int e = 0; e < 4; e++) acc[mi][nj][e] = 0.f;

#pragma unroll
  for (int k0 = 0; k0 < 64; k0 += 8) {
    uint32_t af[2][4];
#pragma unroll
    for (int mi = 0; mi < 2; mi++) {
      const float* ap = A + (k0 + qc) * PW + r0 + mi * 16 + qr;
      af[mi][0] = f2t(ap[0]);
      af[mi][1] = f2t(ap[8]);
      af[mi][2] = f2t(ap[4 * PW]);
      af[mi][3] = f2t(ap[4 * PW + 8]);
    }
    uint32_t bf[2][2];
#pragma unroll
    for (int nj = 0; nj < 2; nj++) {
      const float* bp = WB + (c0 + nj * 8 + qr) * PX + k0 + qc;
      bf[nj][0] = fu(bp[0]);
      bf[nj][1] = fu(bp[4]);
    }
#pragma unroll
    for (int mi = 0; mi < 2; mi++)
#pragma unroll
      for (int nj = 0; nj < 2; nj++)
        mma8(acc[mi][nj], af[mi][0], af[mi][1], af[mi][2], af[mi][3], bf[nj][0], bf[nj][1]);
  }

#pragma unroll
  for (int mi = 0; mi < 2; mi++) {
    const int ra = r0 + mi * 16 + qr;
#pragma unroll
    for (int nj = 0; nj < 2; nj++) {
      const int cc = c0 + nj * 8 + 2 * qc;
      const int cw = cc >> 1;
      const float m0 = mean[ra], rs0 = rstd[ra];
      const float m1 = mean[ra + 8], rs1 = rstd[ra + 8];
      const float ta = t1[cc], tb = t1[cc + 1];
      const float ua = t2[cc], ub = t2[cc + 1];
      const float v0 = rs0 * (acc[mi][nj][0] - m0 * ta) + ua;
      const float v1 = rs0 * (acc[mi][nj][1] - m0 * tb) + ub;
      const float v2 = rs1 * (acc[mi][nj][2] - m1 * ta) + ua;
      const float v3 = rs1 * (acc[mi][nj][3] - m1 * tb) + ub;
      Qb[ra * PQ + cw] = bfpack(v0, v1);
      Qb[(ra + 8) * PQ + cw] = bfpack(v2, v3);
    }
  }
}

// V gemm, output-transposed (R15-proven): Vt[c_out][w], bf16x2 pairs-along-w local.
__device__ __forceinline__ void gemm_vT(
    const float* __restrict__ X, const float* __restrict__ WB,
    uint32_t* __restrict__ Vb, int wid, int qr, int qc) {
  const int r0 = (wid & 3) * 16;   // c_out
  const int c0 = (wid >> 2) * 32;  // w
  float acc[4][4];
#pragma unroll
  for (int nj = 0; nj < 4; nj++)
#pragma unroll
    for (int e = 0; e < 4; e++) acc[nj][e] = 0.f;

#pragma unroll
  for (int k0 = 0; k0 < 64; k0 += 8) {
    const float* ap = WB + (r0 + qr) * PX + k0 + qc;
    uint32_t a0 = fu(ap[0]);
    uint32_t a1 = fu(ap[8 * PX]);
    uint32_t a2 = fu(ap[4]);
    uint32_t a3 = fu(ap[8 * PX + 4]);
    uint32_t bf[4][2];
#pragma unroll
    for (int nj = 0; nj < 4; nj++) {
      const float* bp = X + (k0 + qc) * PW + c0 + nj * 8 + qr;
      bf[nj][0] = f2t(bp[0]);
      bf[nj][1] = f2t(bp[4 * PW]);
    }
#pragma unroll
    for (int nj = 0; nj < 4; nj++)
      mma8(acc[nj], a0, a1, a2, a3, bf[nj][0], bf[nj][1]);
  }

  const int ra = r0 + qr;
#pragma unroll
  for (int nj = 0; nj < 4; nj++) {
    const int cw = (c0 >> 1) + nj * 4 + qc;
    Vb[ra * PBW + cw] = bfpack(acc[nj][0], acc[nj][1]);
    Vb[(ra + 8) * PBW + cw] = bfpack(acc[nj][2], acc[nj][3]);
  }
}

// E = exp(Q K^T / 8) via bf16 mma16 (R15-proven); Eb pairs-along-v + partials.
__device__ __forceinline__ void gemm_s16(
    const uint32_t* __restrict__ Qb, const uint32_t* __restrict__ Kb,
    uint32_t* __restrict__ Eb, float* __restrict__ rowp, float* __restrict__ colp,
    int wid, int qr, int qc) {
  const int r0 = (wid & 3) * 32;
  const int c0 = (wid >> 2) * 32;
  float acc[2][4][4];
#pragma unroll
  for (int mi = 0; mi < 2; mi++)
#pragma unroll
    for (int nj = 0; nj < 4; nj++)
#pragma unroll
      for (int e = 0; e < 4; e++) acc[mi][nj][e] = 0.f;

#pragma unroll
  for (int k0 = 0; k0 < 64; k0 += 16) {
    const int kw = (k0 >> 1) + qc;
    uint32_t af[2][4];
#pragma unroll
    for (int mi = 0; mi < 2; mi++) {
      const int r = r0 + mi * 16 + qr;
      af[mi][0] = Qb[r * PQ + kw];
      af[mi][1] = Qb[(r + 8) * PQ + kw];
      af[mi][2] = Qb[r * PQ + kw + 4];
      af[mi][3] = Qb[(r + 8) * PQ + kw + 4];
    }
    uint32_t bf[4][2];
#pragma unroll
    for (int nj = 0; nj < 4; nj++) {
      const int cc = c0 + nj * 8 + qr;
      bf[nj][0] = Kb[cc * PQ + kw];
      bf[nj][1] = Kb[cc * PQ + kw + 4];
    }
#pragma unroll
    for (int mi = 0; mi < 2; mi++)
#pragma unroll
      for (int nj = 0; nj < 4; nj++)
        mma16(acc[mi][nj], af[mi][0], af[mi][1], af[mi][2], af[mi][3], bf[nj][0], bf[nj][1]);
  }

  float rs0[2] = {0.f, 0.f}, rs1[2] = {0.f, 0.f};
  float cs0[4] = {0.f, 0.f, 0.f, 0.f}, cs1[4] = {0.f, 0.f, 0.f, 0.f};
#pragma unroll
  for (int mi = 0; mi < 2; mi++) {
    const int ra = r0 + mi * 16 + qr;
#pragma unroll
    for (int nj = 0; nj < 4; nj++) {
      const int cw = (c0 >> 1) + nj * 4 + qc;
      const float e0 = __expf(0.125f * acc[mi][nj][0]);
      const float e1 = __expf(0.125f * acc[mi][nj][1]);
      const float e2 = __expf(0.125f * acc[mi][nj][2]);
      const float e3 = __expf(0.125f * acc[mi][nj][3]);
      Eb[ra * PBW + cw] = bfpack(e0, e1);
      Eb[(ra + 8) * PBW + cw] = bfpack(e2, e3);
      rs0[mi] += e0 + e1;
      rs1[mi] += e2 + e3;
      cs0[nj] += e0 + e2;
      cs1[nj] += e1 + e3;
    }
  }
#pragma unroll
  for (int mi = 0; mi < 2; mi++) {
    rs0[mi] += __shfl_xor_sync(0xffffffffu, rs0[mi], 1);
    rs0[mi] += __shfl_xor_sync(0xffffffffu, rs0[mi], 2);
    rs1[mi] += __shfl_xor_sync(0xffffffffu, rs1[mi], 1);
    rs1[mi] += __shfl_xor_sync(0xffffffffu, rs1[mi], 2);
  }
  if (qc == 0) {
    float* rp = rowp + (wid >> 2) * 128;
#pragma unroll
    for (int mi = 0; mi < 2; mi++) {
      rp[r0 + mi * 16 + qr] = rs0[mi];
      rp[r0 + mi * 16 + qr + 8] = rs1[mi];
    }
  }
#pragma unroll
  for (int nj = 0; nj < 4; nj++) {
    cs0[nj] += __shfl_xor_sync(0xffffffffu, cs0[nj], 4);
    cs0[nj] += __shfl_xor_sync(0xffffffffu, cs0[nj], 8);
    cs0[nj] += __shfl_xor_sync(0xffffffffu, cs0[nj], 16);
    cs1[nj] += __shfl_xor_sync(0xffffffffu, cs1[nj], 4);
    cs1[nj] += __shfl_xor_sync(0xffffffffu, cs1[nj], 8);
    cs1[nj] += __shfl_xor_sync(0xffffffffu, cs1[nj], 16);
  }
  if (qr == 0) {
    float* cp = colp + (wid & 3) * 128;
#pragma unroll
    for (int nj = 0; nj < 4; nj++) {
      cp[c0 + nj * 8 + 2 * qc] = cs0[nj];
      cp[c0 + nj * 8 + 2 * qc + 1] = cs1[nj];
    }
  }
}

// out_l (R15-proven): XL[c][w] += invrow[w] * (E @ V2)[w][c]. bf16 mma16, K=128.
__device__ __forceinline__ void gemm_out_l(
    const uint32_t* __restrict__ Eb, const uint32_t* __restrict__ V2b,
    float* __restrict__ XL, const float* __restrict__ invrow, int wid, int qr, int qc) {
  const int r0 = (wid & 3) * 32;
  const int c0 = (wid >> 2) * 16;
  float acc[2][2][4];
#pragma unroll
  for (int mi = 0; mi < 2; mi++)
#pragma unroll
    for (int nj = 0; nj < 2; nj++)
#pragma unroll
      for (int e = 0; e < 4; e++) acc[mi][nj][e] = 0.f;

#pragma unroll
  for (int k0 = 0; k0 < 128; k0 += 16) {
    const int kw = (k0 >> 1) + qc;
    uint32_t af[2][4];
#pragma unroll
    for (int mi = 0; mi < 2; mi++) {
      const int r = r0 + mi * 16 + qr;
      af[mi][0] = Eb[r * PBW + kw];
      af[mi][1] = Eb[(r + 8) * PBW + kw];
      af[mi][2] = Eb[r * PBW + kw + 4];
      af[mi][3] = Eb[(r + 8) * PBW + kw + 4];
    }
    uint32_t bf[2][2];
#pragma unroll
    for (int nj = 0; nj < 2; nj++) {
      const int cc = c0 + nj * 8 + qr;
      bf[nj][0] = V2b[cc * PBW + kw];
      bf[nj][1] = V2b[cc * PBW + kw + 4];
    }
#pragma unroll
    for (int mi = 0; mi < 2; mi++)
#pragma unroll
      for (int nj = 0; nj < 2; nj++)
        mma16(acc[mi][nj], af[mi][0], af[mi][1], af[mi][2], af[mi][3], bf[nj][0], bf[nj][1]);
  }

#pragma unroll
  for (int mi = 0; mi < 2; mi++) {
    const int ra = r0 + mi * 16 + qr;
    const float ir0 = invrow[ra], ir1 = invrow[ra + 8];
#pragma unroll
    for (int nj = 0; nj < 2; nj++) {
      const int cc = c0 + nj * 8 + 2 * qc;
      XL[cc * PW + ra] += acc[mi][nj][0] * ir0;
      XL[(cc + 1) * PW + ra] += acc[mi][nj][1] * ir0;
      XL[cc * PW + ra + 8] += acc[mi][nj][2] * ir1;
      XL[(cc + 1) * PW + ra + 8] += acc[mi][nj][3] * ir1;
    }
  }
}

// out_h (R15-proven): out_h^T[c][w] = sum_u V1[u][c] * Ebt[w][u]. bf16 mma16.
__device__ __forceinline__ void gemm_out_h(
    const uint32_t* __restrict__ Ebt, const uint32_t* __restrict__ V1b,
    float* __restrict__ XH, const float* __restrict__ invcol, int wid, int qr, int qc) {
  const int r0 = (wid & 3) * 16;   // c
  const int c0 = (wid >> 2) * 32;  // w
  float acc[4][4];
#pragma unroll
  for (int nj = 0; nj < 4; nj++)
#pragma unroll
    for (int e = 0; e < 4; e++) acc[nj][e] = 0.f;

#pragma unroll
  for (int k0 = 0; k0 < 128; k0 += 16) {
    const int kw = (k0 >> 1) + qc;
    const int rr = r0 + qr;
    uint32_t a0 = V1b[rr * PBW + kw];
    uint32_t a1 = V1b[(rr + 8) * PBW + kw];
    uint32_t a2 = V1b[rr * PBW + kw + 4];
    uint32_t a3 = V1b[(rr + 8) * PBW + kw + 4];
    uint32_t bf[4][2];
#pragma unroll
    for (int nj = 0; nj < 4; nj++) {
      const int cc = c0 + nj * 8 + qr;
      bf[nj][0] = Ebt[cc * PBW + kw];
      bf[nj][1] = Ebt[cc * PBW + kw + 4];
    }
#pragma unroll
    for (int nj = 0; nj < 4; nj++)
      mma16(acc[nj], a0, a1, a2, a3, bf[nj][0], bf[nj][1]);
  }

  const int ra = r0 + qr;
#pragma unroll
  for (int nj = 0; nj < 4; nj++) {
    const int w0 = c0 + nj * 8 + 2 * qc;
    const int w1 = w0 + 1;
    XH[ra * PW + w0] += acc[nj][0] * invcol[w0];
    XH[ra * PW + w1] += acc[nj][1] * invcol[w1];
    XH[(ra + 8) * PW + w0] += acc[nj][2] * invcol[w0];
    XH[(ra + 8) * PW + w1] += acc[nj][3] * invcol[w1];
  }
}

__global__ __launch_bounds__(NTHR)
void scam_kernel(const float* __restrict__ x_l, const float* __restrict__ x_h,
                 const float* __restrict__ g1, const float* __restrict__ b1,
                 const float* __restrict__ g2, const float* __restrict__ b2,
                 const float* __restrict__ Wq, const float* __restrict__ Wk,
                 const float* __restrict__ Wv1, const float* __restrict__ Wv2,
                 float* __restrict__ out_l, float* __restrict__ out_h) {
  extern __shared__ float sm[];
  float* XL = sm + OFF_XL;
  float* XH = sm + OFF_XH;
  uint32_t* Qb = (uint32_t*)(sm + OFF_QB);
  uint32_t* Kb = (uint32_t*)(sm + OFF_KB);
  uint32_t* V1b = (uint32_t*)(sm + OFF_QB);  // aliases Qb (dead after gemm_s)
  uint32_t* V2b = (uint32_t*)(sm + OFF_KB);  // aliases Kb
  uint32_t* Eb = (uint32_t*)(sm + OFF_EB);
  uint32_t* Ebt = (uint32_t*)(sm + OFF_EBT);
  float* WB = sm + OFF_WB;
  float* WB2 = sm + OFF_WB2;
  float* rowp = sm + OFF_ROWP;
  float* colp = sm + OFF_COLP;
  float* meanl = sm + OFF_STAT;
  float* rstdl = meanl + 128;
  float* meanh = rstdl + 128;
  float* rstdh = meanh + 128;
  float* t1q = sm + OFF_T;
  float* t2q = t1q + 64;
  float* t1k = t2q + 64;
  float* t2k = t1k + 64;
  float* invrow = sm + OFF_INV;
  float* invcol = invrow + 128;

  const int tid = threadIdx.x;
  const int lane = tid & 31;
  const int wid = tid >> 5;
  const int qr = lane >> 2;
  const int qc = lane & 3;
  const int bh = blockIdx.x;
  const int b = bh >> 7;
  const int h = bh & 127;
  const size_t planeoff = ((size_t)b * kC * kH + (size_t)h) * kW;

  // ---- P1: stage x (c-major float4, conflict-free, coalesced) ----
  for (int i = tid; i < kC * (kW / 4); i += NTHR) {
    const int c = i >> 5;
    const int w4 = (i & 31) * 4;
    const size_t goff = planeoff + (size_t)c * PLANE + w4;
    *(float4*)(XL + c * PW + w4) = *(const float4*)(x_l + goff);
    *(float4*)(XH + c * PW + w4) = *(const float4*)(x_h + goff);
  }
  __syncthreads();

  // ---- P2: LN stats (2 thr/row); stage Wq->WB and Wk->WB2 (warp halves) ----
  {
    const int rowid = tid >> 1;
    const int r = rowid & 127;
    const int half = tid & 1;
    const float* src = (rowid < 128 ? XL : XH) + half * 32 * PW + r;
    float s = 0.f, s2 = 0.f;
#pragma unroll
    for (int c = 0; c < 32; c++) {
      const float v = src[c * PW];
      s += v;
      s2 = fmaf(v, v, s2);
    }
    s += __shfl_xor_sync(0xffffffffu, s, 1);
    s2 += __shfl_xor_sync(0xffffffffu, s2, 1);
    if (half == 0) {
      const float m = s * (1.f / 64.f);
      const float var = fmaf(-m, m, s2 * (1.f / 64.f));
      const float rs = rsqrtf(var + 1e-5f);
      if (rowid < 128) { meanl[r] = m; rstdl[r] = rs; }
      else             { meanh[r] = m; rstdh[r] = rs; }
    }
  }
  if (tid < 256) stage_fold256(Wq, g1, b1, WB, t1q, t2q, tid);
  else           stage_fold256(Wk, g2, b2, WB2, t1k, t2k, tid - 256);
  __syncthreads();

  // ---- P3: Q then K, back-to-back (all 16 warps each, no barrier between) ----
  gemm_qk(XL, WB, Qb, wid, qr, qc, meanl, rstdl, t1q, t2q);
  gemm_qk(XH, WB2, Kb, wid, qr, qc, meanh, rstdh, t1k, t2k);
  __syncthreads();

  // ---- P4: E = exp(QK^T/8) + partials; stage Wv1->WB, Wv2->WB2 same phase ----
  gemm_s16(Qb, Kb, Eb, rowp, colp, wid, qr, qc);
  if (tid < 256) stage_raw256(Wv1, WB, tid);
  else           stage_raw256(Wv2, WB2, tid - 256);
  __syncthreads();

  // ---- P5: inverses; Eb->Ebt transpose; V1 then V2 back-to-back ----
  if (tid < 128) {
    invrow[tid] = 1.f / (rowp[tid] + rowp[128 + tid] + rowp[256 + tid] + rowp[384 + tid]);
  } else if (tid < 256) {
    const int c = tid - 128;
    invcol[c] = 1.f / (colp[c] + colp[128 + c] + colp[256 + c] + colp[384 + c]);
  }
  {
    const int rp = (lane >> 2) + 8 * (wid & 7);        // q-pair 0..63
    const int ci0 = (lane & 3) + 4 * (wid >> 3);       // 0..7
#pragma unroll
    for (int cj = 0; cj < 8; cj++) {
      const int cidx = ci0 + 8 * cj;                   // v-pair 0..63
      const uint32_t w0 = Eb[(2 * rp) * PBW + cidx];
      const uint32_t w1 = Eb[(2 * rp + 1) * PBW + cidx];
      Ebt[(2 * cidx) * PBW + rp] = __byte_perm(w0, w1, 0x5410);
      Ebt[(2 * cidx + 1) * PBW + rp] = __byte_perm(w0, w1, 0x7632);
    }
  }
  gemm_vT(XL, WB, V1b, wid, qr, qc);
  gemm_vT(XH, WB2, V2b, wid, qr, qc);
  __syncthreads();

  // ---- P6: out gemms (bf16), smem epilogues into XL/XH ----
  gemm_out_l(Eb, V2b, XL, invrow, wid, qr, qc);
  gemm_out_h(Ebt, V1b, XH, invcol, wid, qr, qc);
  __syncthreads();

  // ---- P7: writeout (conflict-free LDS.128, coalesced STG) ----
  for (int i = tid; i < kC * (kW / 4); i += NTHR) {
    const int c = i >> 5;
    const int w4 = (i & 31) * 4;
    const size_t goff = planeoff + (size_t)c * PLANE + w4;
    *(float4*)(out_l + goff) = *(const float4*)(XL + c * PW + w4);
    *(float4*)(out_h + goff) = *(const float4*)(XH + c * PW + w4);
  }
}

}  // namespace

extern "C" void kernel_launch(void* const* d_in, const int* in_sizes, int n_in,
                              void* d_out, int out_size) {
  const float* x_l = (const float*)d_in[0];
  const float* x_h = (const float*)d_in[1];
  const float* g1 = (const float*)d_in[2];
  const float* b1 = (const float*)d_in[3];
  const float* g2 = (const float*)d_in[4];
  const float* b2 = (const float*)d_in[5];
  const float* Wq = (const float*)d_in[6];
  const float* Wk = (const float*)d_in[7];
  const float* Wv1 = (const float*)d_in[8];
  const float* Wv2 = (const float*)d_in[9];

  float* out = (float*)d_out;
  float* out_l = out;
  float* out_h = out + (size_t)kB * kC * kH * kW;

  const size_t smem = (size_t)SMEM_FLOATS * sizeof(float);  // ~219 KB
  cudaFuncSetAttribute(scam_kernel, cudaFuncAttributeMaxDynamicSharedMemorySize, (int)smem);
  scam_kernel<<<kB * kH, NTHR, smem>>>(x_l, x_h, g1, b1, g2, b2, Wq, Wk, Wv1, Wv2,
                                       out_l, out_h);
}

// round 17
// speedup vs baseline: 1.3521x; 1.3521x over previous
#include <cuda_runtime.h>
#include <cstdint>

namespace {

constexpr int kB = 16, kC = 64, kH = 128, kW = 128;
constexpr int PX = 68;    // float pitch for weight tiles [64][PX]; 68 % 32 == 4
constexpr int PQ = 36;    // word pitch for bf16x2 Q/K tiles [128][PQ]; 36 % 32 == 4
constexpr int PBW = 68;   // word pitch for bf16x2 E/Ebt/V tiles; 68 % 32 == 4
constexpr int PW = 136;   // float pitch for c-major x tiles [64][PW]; 136 % 32 == 8
constexpr int NTHR = 512;
constexpr int PLANE = kH * kW;

// smem float/word offsets
constexpr int OFF_XL  = 0;                    // [64][PW] fp32
constexpr int OFF_XH  = OFF_XL + 64 * PW;     // 8704
constexpr int OFF_QB  = OFF_XH + 64 * PW;     // 17408: Qb [128][PQ]; V1b aliases
constexpr int OFF_KB  = OFF_QB + 128 * PQ;    // 22016: Kb; V2b aliases
constexpr int OFF_EB  = OFF_KB + 128 * PQ;    // 26624: Eb [128][PBW]
constexpr int OFF_EBT = OFF_EB + 128 * PBW;   // 35328: Ebt [128][PBW]
constexpr int OFF_WB  = OFF_EBT + 128 * PBW;  // 44032: WB  [64][PX] fp32
constexpr int OFF_WB2 = OFF_WB + 64 * PX;     // 48384: WB2 [64][PX] fp32
constexpr int OFF_ROWP= OFF_WB2 + 64 * PX;    // 52736
constexpr int OFF_COLP= OFF_ROWP + 512;       // 53248
constexpr int OFF_STAT= OFF_COLP + 512;       // 53760: meanl,rstdl,meanh,rstdh
constexpr int OFF_T   = OFF_STAT + 512;       // 54272: t1q,t2q,t1k,t2k (64 each)
constexpr int OFF_INV = OFF_T + 256;          // 54528: invrow,invcol
constexpr int SMEM_FLOATS = OFF_INV + 256;    // 54784 -> 219,136 B

__device__ __forceinline__ uint32_t f2t(float x) {
  uint32_t r;
  asm("cvt.rna.tf32.f32 %0, %1;" : "=r"(r) : "f"(x));
  return r;
}
__device__ __forceinline__ float tround(float x) { return __uint_as_float(f2t(x)); }
__device__ __forceinline__ uint32_t fu(float x) { return __float_as_uint(x); }

__device__ __forceinline__ uint32_t bfpack(float lo, float hi) {
  uint32_t r;
  asm("cvt.rn.bf16x2.f32 %0, %1, %2;" : "=r"(r) : "f"(hi), "f"(lo));
  return r;
}

__device__ __forceinline__ void mma8(float* c, uint32_t a0, uint32_t a1, uint32_t a2,
                                     uint32_t a3, uint32_t b0, uint32_t b1) {
  asm volatile(
      "mma.sync.aligned.m16n8k8.row.col.f32.tf32.tf32.f32 "
      "{%0,%1,%2,%3},{%4,%5,%6,%7},{%8,%9},{%0,%1,%2,%3};"
      : "+f"(c[0]), "+f"(c[1]), "+f"(c[2]), "+f"(c[3])
      : "r"(a0), "r"(a1), "r"(a2), "r"(a3), "r"(b0), "r"(b1));
}

__device__ __forceinline__ void mma16(float* c, uint32_t a0, uint32_t a1, uint32_t a2,
                                      uint32_t a3, uint32_t b0, uint32_t b1) {
  asm volatile(
      "mma.sync.aligned.m16n8k16.row.col.f32.bf16.bf16.f32 "
      "{%0,%1,%2,%3},{%4,%5,%6,%7},{%8,%9},{%0,%1,%2,%3};"
      : "+f"(c[0]), "+f"(c[1]), "+f"(c[2]), "+f"(c[3])
      : "r"(a0), "r"(a1), "r"(a2), "r"(a3), "r"(b0), "r"(b1));
}

// 64x64 weight fold, fp32->tf32; 512 thr: 8 elements per thread (R15-proven).
__device__ __forceinline__ void load_weight_fold(
    const float* __restrict__ Wsrc, const float* __restrict__ g,
    const float* __restrict__ bb, float* __restrict__ WB,
    float* __restrict__ t1, float* __restrict__ t2, int tid) {
  const int j = tid >> 3;
  const int c0 = (tid & 7) * 8;
  float s1 = 0.f, s2 = 0.f;
#pragma unroll
  for (int u = 0; u < 8; u++) {
    const int c = c0 + u;
    const float raw = Wsrc[j * 64 + c];
    const float wf = tround(raw * g[c]);
    WB[j * PX + c] = wf;
    s1 += wf;
    s2 += raw * bb[c];
  }
  s1 += __shfl_xor_sync(0xffffffffu, s1, 1);
  s1 += __shfl_xor_sync(0xffffffffu, s1, 2);
  s1 += __shfl_xor_sync(0xffffffffu, s1, 4);
  s2 += __shfl_xor_sync(0xffffffffu, s2, 1);
  s2 += __shfl_xor_sync(0xffffffffu, s2, 2);
  s2 += __shfl_xor_sync(0xffffffffu, s2, 4);
  if ((tid & 7) == 0) { t1[j] = s1; t2[j] = s2; }
}

__device__ __forceinline__ void load_weight_raw(
    const float* __restrict__ Wsrc, float* __restrict__ WB, int tid) {
  const int j = tid >> 3;
  const int c0 = (tid & 7) * 8;
#pragma unroll
  for (int u = 0; u < 8; u++) WB[j * PX + c0 + u] = tround(Wsrc[j * 64 + c0 + u]);
}

// Q/K gemm (R15-proven): C = LN(A) @ WB^T -> Qb[w][c/2] bf16 pairs-along-c.
// A c-major [c][PW]. 16 warps, 4(m)x4(n), 32x16 tiles.
__device__ __forceinline__ void gemm_qk(
    const float* __restrict__ A, const float* __restrict__ WB, uint32_t* __restrict__ Qb,
    int wid, int qr, int qc, const float* __restrict__ mean,
    const float* __restrict__ rstd, const float* __restrict__ t1,
    const float* __restrict__ t2) {
  const int r0 = (wid & 3) * 32;
  const int c0 = (wid >> 2) * 16;
  float acc[2][2][4];
#pragma unroll
  for (int mi = 0; mi < 2; mi++)
#pragma unroll
    for (int nj = 0; nj < 2; nj++)
#pragma unroll
      for (int e = 0; e < 4; e++) acc[mi][nj][e] = 0.f;

#pragma unroll
  for (int k0 = 0; k0 < 64; k0 += 8) {
    uint32_t af[2][4];
#pragma unroll
    for (int mi = 0; mi < 2; mi++) {
      const float* ap = A + (k0 + qc) * PW + r0 + mi * 16 + qr;
      af[mi][0] = f2t(ap[0]);
      af[mi][1] = f2t(ap[8]);
      af[mi][2] = f2t(ap[4 * PW]);
      af[mi][3] = f2t(ap[4 * PW + 8]);
    }
    uint32_t bf[2][2];
#pragma unroll
    for (int nj = 0; nj < 2; nj++) {
      const float* bp = WB + (c0 + nj * 8 + qr) * PX + k0 + qc;
      bf[nj][0] = fu(bp[0]);
      bf[nj][1] = fu(bp[4]);
    }
#pragma unroll
    for (int mi = 0; mi < 2; mi++)
#pragma unroll
      for (int nj = 0; nj < 2; nj++)
        mma8(acc[mi][nj], af[mi][0], af[mi][1], af[mi][2], af[mi][3], bf[nj][0], bf[nj][1]);
  }

#pragma unroll
  for (int mi = 0; mi < 2; mi++) {
    const int ra = r0 + mi * 16 + qr;
#pragma unroll
    for (int nj = 0; nj < 2; nj++) {
      const int cc = c0 + nj * 8 + 2 * qc;
      const int cw = cc >> 1;
      const float m0 = mean[ra], rs0 = rstd[ra];
      const float m1 = mean[ra + 8], rs1 = rstd[ra + 8];
      const float ta = t1[cc], tb = t1[cc + 1];
      const float ua = t2[cc], ub = t2[cc + 1];
      const float v0 = rs0 * (acc[mi][nj][0] - m0 * ta) + ua;
      const float v1 = rs0 * (acc[mi][nj][1] - m0 * tb) + ub;
      const float v2 = rs1 * (acc[mi][nj][2] - m1 * ta) + ua;
      const float v3 = rs1 * (acc[mi][nj][3] - m1 * tb) + ub;
      Qb[ra * PQ + cw] = bfpack(v0, v1);
      Qb[(ra + 8) * PQ + cw] = bfpack(v2, v3);
    }
  }
}

// V gemm, output-transposed (R15-proven): Vt[c_out][w], bf16x2 pairs-along-w local.
__device__ __forceinline__ void gemm_vT(
    const float* __restrict__ X, const float* __restrict__ WB,
    uint32_t* __restrict__ Vb, int wid, int qr, int qc) {
  const int r0 = (wid & 3) * 16;   // c_out
  const int c0 = (wid >> 2) * 32;  // w
  float acc[4][4];
#pragma unroll
  for (int nj = 0; nj < 4; nj++)
#pragma unroll
    for (int e = 0; e < 4; e++) acc[nj][e] = 0.f;

#pragma unroll
  for (int k0 = 0; k0 < 64; k0 += 8) {
    const float* ap = WB + (r0 + qr) * PX + k0 + qc;
    uint32_t a0 = fu(ap[0]);
    uint32_t a1 = fu(ap[8 * PX]);
    uint32_t a2 = fu(ap[4]);
    uint32_t a3 = fu(ap[8 * PX + 4]);
    uint32_t bf[4][2];
#pragma unroll
    for (int nj = 0; nj < 4; nj++) {
      const float* bp = X + (k0 + qc) * PW + c0 + nj * 8 + qr;
      bf[nj][0] = f2t(bp[0]);
      bf[nj][1] = f2t(bp[4 * PW]);
    }
#pragma unroll
    for (int nj = 0; nj < 4; nj++)
      mma8(acc[nj], a0, a1, a2, a3, bf[nj][0], bf[nj][1]);
  }

  const int ra = r0 + qr;
#pragma unroll
  for (int nj = 0; nj < 4; nj++) {
    const int cw = (c0 >> 1) + nj * 4 + qc;
    Vb[ra * PBW + cw] = bfpack(acc[nj][0], acc[nj][1]);
    Vb[(ra + 8) * PBW + cw] = bfpack(acc[nj][2], acc[nj][3]);
  }
}

// E = exp(Q K^T / 8) via bf16 mma16 (R15-proven); Eb pairs-along-v + partials.
__device__ __forceinline__ void gemm_s16(
    const uint32_t* __restrict__ Qb, const uint32_t* __restrict__ Kb,
    uint32_t* __restrict__ Eb, float* __restrict__ rowp, float* __restrict__ colp,
    int wid, int qr, int qc) {
  const int r0 = (wid & 3) * 32;
  const int c0 = (wid >> 2) * 32;
  float acc[2][4][4];
#pragma unroll
  for (int mi = 0; mi < 2; mi++)
#pragma unroll
    for (int nj = 0; nj < 4; nj++)
#pragma unroll
      for (int e = 0; e < 4; e++) acc[mi][nj][e] = 0.f;

#pragma unroll
  for (int k0 = 0; k0 < 64; k0 += 16) {
    const int kw = (k0 >> 1) + qc;
    uint32_t af[2][4];
#pragma unroll
    for (int mi = 0; mi < 2; mi++) {
      const int r = r0 + mi * 16 + qr;
      af[mi][0] = Qb[r * PQ + kw];
      af[mi][1] = Qb[(r + 8) * PQ + kw];
      af[mi][2] = Qb[r * PQ + kw + 4];
      af[mi][3] = Qb[(r + 8) * PQ + kw + 4];
    }
    uint32_t bf[4][2];
#pragma unroll
    for (int nj = 0; nj < 4; nj++) {
      const int cc = c0 + nj * 8 + qr;
      bf[nj][0] = Kb[cc * PQ + kw];
      bf[nj][1] = Kb[cc * PQ + kw + 4];
    }
#pragma unroll
    for (int mi = 0; mi < 2; mi++)
#pragma unroll
      for (int nj = 0; nj < 4; nj++)
        mma16(acc[mi][nj], af[mi][0], af[mi][1], af[mi][2], af[mi][3], bf[nj][0], bf[nj][1]);
  }

  float rs0[2] = {0.f, 0.f}, rs1[2] = {0.f, 0.f};
  float cs0[4] = {0.f, 0.f, 0.f, 0.f}, cs1[4] = {0.f, 0.f, 0.f, 0.f};
#pragma unroll
  for (int mi = 0; mi < 2; mi++) {
    const int ra = r0 + mi * 16 + qr;
#pragma unroll
    for (int nj = 0; nj < 4; nj++) {
      const int cw = (c0 >> 1) + nj * 4 + qc;
      const float e0 = __expf(0.125f * acc[mi][nj][0]);
      const float e1 = __expf(0.125f * acc[mi][nj][1]);
      const float e2 = __expf(0.125f * acc[mi][nj][2]);
      const float e3 = __expf(0.125f * acc[mi][nj][3]);
      Eb[ra * PBW + cw] = bfpack(e0, e1);
      Eb[(ra + 8) * PBW + cw] = bfpack(e2, e3);
      rs0[mi] += e0 + e1;
      rs1[mi] += e2 + e3;
      cs0[nj] += e0 + e2;
      cs1[nj] += e1 + e3;
    }
  }
#pragma unroll
  for (int mi = 0; mi < 2; mi++) {
    rs0[mi] += __shfl_xor_sync(0xffffffffu, rs0[mi], 1);
    rs0[mi] += __shfl_xor_sync(0xffffffffu, rs0[mi], 2);
    rs1[mi] += __shfl_xor_sync(0xffffffffu, rs1[mi], 1);
    rs1[mi] += __shfl_xor_sync(0xffffffffu, rs1[mi], 2);
  }
  if (qc == 0) {
    float* rp = rowp + (wid >> 2) * 128;
#pragma unroll
    for (int mi = 0; mi < 2; mi++) {
      rp[r0 + mi * 16 + qr] = rs0[mi];
      rp[r0 + mi * 16 + qr + 8] = rs1[mi];
    }
  }
#pragma unroll
  for (int nj = 0; nj < 4; nj++) {
    cs0[nj] += __shfl_xor_sync(0xffffffffu, cs0[nj], 4);
    cs0[nj] += __shfl_xor_sync(0xffffffffu, cs0[nj], 8);
    cs0[nj] += __shfl_xor_sync(0xffffffffu, cs0[nj], 16);
    cs1[nj] += __shfl_xor_sync(0xffffffffu, cs1[nj], 4);
    cs1[nj] += __shfl_xor_sync(0xffffffffu, cs1[nj], 8);
    cs1[nj] += __shfl_xor_sync(0xffffffffu, cs1[nj], 16);
  }
  if (qr == 0) {
    float* cp = colp + (wid & 3) * 128;
#pragma unroll
    for (int nj = 0; nj < 4; nj++) {
      cp[c0 + nj * 8 + 2 * qc] = cs0[nj];
      cp[c0 + nj * 8 + 2 * qc + 1] = cs1[nj];
    }
  }
}

// out_l (R15-proven): XL[c][w] += invrow[w] * (E @ V2)[w][c]. bf16 mma16, K=128.
__device__ __forceinline__ void gemm_out_l(
    const uint32_t* __restrict__ Eb, const uint32_t* __restrict__ V2b,
    float* __restrict__ XL, const float* __restrict__ invrow, int wid, int qr, int qc) {
  const int r0 = (wid & 3) * 32;
  const int c0 = (wid >> 2) * 16;
  float acc[2][2][4];
#pragma unroll
  for (int mi = 0; mi < 2; mi++)
#pragma unroll
    for (int nj = 0; nj < 2; nj++)
#pragma unroll
      for (int e = 0; e < 4; e++) acc[mi][nj][e] = 0.f;

#pragma unroll
  for (int k0 = 0; k0 < 128; k0 += 16) {
    const int kw = (k0 >> 1) + qc;
    uint32_t af[2][4];
#pragma unroll
    for (int mi = 0; mi < 2; mi++) {
      const int r = r0 + mi * 16 + qr;
      af[mi][0] = Eb[r * PBW + kw];
      af[mi][1] = Eb[(r + 8) * PBW + kw];
      af[mi][2] = Eb[r * PBW + kw + 4];
      af[mi][3] = Eb[(r + 8) * PBW + kw + 4];
    }
    uint32_t bf[2][2];
#pragma unroll
    for (int nj = 0; nj < 2; nj++) {
      const int cc = c0 + nj * 8 + qr;
      bf[nj][0] = V2b[cc * PBW + kw];
      bf[nj][1] = V2b[cc * PBW + kw + 4];
    }
#pragma unroll
    for (int mi = 0; mi < 2; mi++)
#pragma unroll
      for (int nj = 0; nj < 2; nj++)
        mma16(acc[mi][nj], af[mi][0], af[mi][1], af[mi][2], af[mi][3], bf[nj][0], bf[nj][1]);
  }

#pragma unroll
  for (int mi = 0; mi < 2; mi++) {
    const int ra = r0 + mi * 16 + qr;
    const float ir0 = invrow[ra], ir1 = invrow[ra + 8];
#pragma unroll
    for (int nj = 0; nj < 2; nj++) {
      const int cc = c0 + nj * 8 + 2 * qc;
      XL[cc * PW + ra] += acc[mi][nj][0] * ir0;
      XL[(cc + 1) * PW + ra] += acc[mi][nj][1] * ir0;
      XL[cc * PW + ra + 8] += acc[mi][nj][2] * ir1;
      XL[(cc + 1) * PW + ra + 8] += acc[mi][nj][3] * ir1;
    }
  }
}

// out_h (R15-proven): out_h^T[c][w] = sum_u V1[u][c] * Ebt[w][u]. bf16 mma16.
__device__ __forceinline__ void gemm_out_h(
    const uint32_t* __restrict__ Ebt, const uint32_t* __restrict__ V1b,
    float* __restrict__ XH, const float* __restrict__ invcol, int wid, int qr, int qc) {
  const int r0 = (wid & 3) * 16;   // c
  const int c0 = (wid >> 2) * 32;  // w
  float acc[4][4];
#pragma unroll
  for (int nj = 0; nj < 4; nj++)
#pragma unroll
    for (int e = 0; e < 4; e++) acc[nj][e] = 0.f;

#pragma unroll
  for (int k0 = 0; k0 < 128; k0 += 16) {
    const int kw = (k0 >> 1) + qc;
    const int rr = r0 + qr;
    uint32_t a0 = V1b[rr * PBW + kw];
    uint32_t a1 = V1b[(rr + 8) * PBW + kw];
    uint32_t a2 = V1b[rr * PBW + kw + 4];
    uint32_t a3 = V1b[(rr + 8) * PBW + kw + 4];
    uint32_t bf[4][2];
#pragma unroll
    for (int nj = 0; nj < 4; nj++) {
      const int cc = c0 + nj * 8 + qr;
      bf[nj][0] = Ebt[cc * PBW + kw];
      bf[nj][1] = Ebt[cc * PBW + kw + 4];
    }
#pragma unroll
    for (int nj = 0; nj < 4; nj++)
      mma16(acc[nj], a0, a1, a2, a3, bf[nj][0], bf[nj][1]);
  }

  const int ra = r0 + qr;
#pragma unroll
  for (int nj = 0; nj < 4; nj++) {
    const int w0 = c0 + nj * 8 + 2 * qc;
    const int w1 = w0 + 1;
    XH[ra * PW + w0] += acc[nj][0] * invcol[w0];
    XH[ra * PW + w1] += acc[nj][1] * invcol[w1];
    XH[(ra + 8) * PW + w0] += acc[nj][2] * invcol[w0];
    XH[(ra + 8) * PW + w1] += acc[nj][3] * invcol[w1];
  }
}

__global__ __launch_bounds__(NTHR)
void scam_kernel(const float* __restrict__ x_l, const float* __restrict__ x_h,
                 const float* __restrict__ g1, const float* __restrict__ b1,
                 const float* __restrict__ g2, const float* __restrict__ b2,
                 const float* __restrict__ Wq, const float* __restrict__ Wk,
                 const float* __restrict__ Wv1, const float* __restrict__ Wv2,
                 float* __restrict__ out_l, float* __restrict__ out_h) {
  extern __shared__ float sm[];
  float* XL = sm + OFF_XL;
  float* XH = sm + OFF_XH;
  uint32_t* Qb = (uint32_t*)(sm + OFF_QB);
  uint32_t* Kb = (uint32_t*)(sm + OFF_KB);
  uint32_t* V1b = (uint32_t*)(sm + OFF_QB);  // aliases Qb (dead after gemm_s)
  uint32_t* V2b = (uint32_t*)(sm + OFF_KB);  // aliases Kb
  uint32_t* Eb = (uint32_t*)(sm + OFF_EB);
  uint32_t* Ebt = (uint32_t*)(sm + OFF_EBT);
  float* WB = sm + OFF_WB;
  float* WB2 = sm + OFF_WB2;
  float* rowp = sm + OFF_ROWP;
  float* colp = sm + OFF_COLP;
  float* meanl = sm + OFF_STAT;
  float* rstdl = meanl + 128;
  float* meanh = rstdl + 128;
  float* rstdh = meanh + 128;
  float* t1q = sm + OFF_T;
  float* t2q = t1q + 64;
  float* t1k = t2q + 64;
  float* t2k = t1k + 64;
  float* invrow = sm + OFF_INV;
  float* invcol = invrow + 128;

  const int tid = threadIdx.x;
  const int lane = tid & 31;
  const int wid = tid >> 5;
  const int qr = lane >> 2;
  const int qc = lane & 3;
  const int bh = blockIdx.x;
  const int b = bh >> 7;
  const int h = bh & 127;
  const size_t planeoff = ((size_t)b * kC * kH + (size_t)h) * kW;

  // ---- P1: stage x (c-major float4, conflict-free, coalesced) ----
  for (int i = tid; i < kC * (kW / 4); i += NTHR) {
    const int c = i >> 5;
    const int w4 = (i & 31) * 4;
    const size_t goff = planeoff + (size_t)c * PLANE + w4;
    *(float4*)(XL + c * PW + w4) = *(const float4*)(x_l + goff);
    *(float4*)(XH + c * PW + w4) = *(const float4*)(x_h + goff);
  }
  __syncthreads();

  // ---- P2: LN stats (2 thr/row) + stage Wq->WB ----
  {
    const int rowid = tid >> 1;
    const int r = rowid & 127;
    const int half = tid & 1;
    const float* src = (rowid < 128 ? XL : XH) + half * 32 * PW + r;
    float s = 0.f, s2 = 0.f;
#pragma unroll
    for (int c = 0; c < 32; c++) {
      const float v = src[c * PW];
      s += v;
      s2 = fmaf(v, v, s2);
    }
    s += __shfl_xor_sync(0xffffffffu, s, 1);
    s2 += __shfl_xor_sync(0xffffffffu, s2, 1);
    if (half == 0) {
      const float m = s * (1.f / 64.f);
      const float var = fmaf(-m, m, s2 * (1.f / 64.f));
      const float rs = rsqrtf(var + 1e-5f);
      if (rowid < 128) { meanl[r] = m; rstdl[r] = rs; }
      else             { meanh[r] = m; rstdh[r] = rs; }
    }
  }
  load_weight_fold(Wq, g1, b1, WB, t1q, t2q, tid);
  __syncthreads();

  // ---- P3: Q gemm; Wk staged into WB2 in same phase (overlap, R15 pattern) ----
  gemm_qk(XL, WB, Qb, wid, qr, qc, meanl, rstdl, t1q, t2q);
  load_weight_fold(Wk, g2, b2, WB2, t1k, t2k, tid);
  __syncthreads();

  // ---- P4: K gemm (sole GEMM in phase) ----
  gemm_qk(XH, WB2, Kb, wid, qr, qc, meanh, rstdh, t1k, t2k);
  __syncthreads();

  // ---- P5: E = exp(QK^T/8) + partials; Wv1 staged same phase ----
  gemm_s16(Qb, Kb, Eb, rowp, colp, wid, qr, qc);
  load_weight_raw(Wv1, WB, tid);
  __syncthreads();

  // ---- P6: inverses; Eb->Ebt transpose; V1 gemm; Wv2 staged same phase ----
  if (tid < 128) {
    invrow[tid] = 1.f / (rowp[tid] + rowp[128 + tid] + rowp[256 + tid] + rowp[384 + tid]);
  } else if (tid < 256) {
    const int c = tid - 128;
    invcol[c] = 1.f / (colp[c] + colp[128 + c] + colp[256 + c] + colp[384 + c]);
  }
  {
    const int rp = (lane >> 2) + 8 * (wid & 7);        // q-pair 0..63
    const int ci0 = (lane & 3) + 4 * (wid >> 3);       // 0..7
#pragma unroll
    for (int cj = 0; cj < 8; cj++) {
      const int cidx = ci0 + 8 * cj;                   // v-pair 0..63
      const uint32_t w0 = Eb[(2 * rp) * PBW + cidx];
      const uint32_t w1 = Eb[(2 * rp + 1) * PBW + cidx];
      Ebt[(2 * cidx) * PBW + rp] = __byte_perm(w0, w1, 0x5410);
      Ebt[(2 * cidx + 1) * PBW + rp] = __byte_perm(w0, w1, 0x7632);
    }
  }
  gemm_vT(XL, WB, V1b, wid, qr, qc);
  load_weight_raw(Wv2, WB2, tid);
  __syncthreads();

  // ---- P7: V2 gemm (sole GEMM in phase) ----
  gemm_vT(XH, WB2, V2b, wid, qr, qc);
  __syncthreads();

  // ---- P8: out gemms (bf16), smem epilogues into XL/XH ----
  gemm_out_l(Eb, V2b, XL, invrow, wid, qr, qc);
  gemm_out_h(Ebt, V1b, XH, invcol, wid, qr, qc);
  __syncthreads();

  // ---- P9: writeout (conflict-free LDS.128, coalesced STG) ----
  for (int i = tid; i < kC * (kW / 4); i += NTHR) {
    const int c = i >> 5;
    const int w4 = (i & 31) * 4;
    const size_t goff = planeoff + (size_t)c * PLANE + w4;
    *(float4*)(out_l + goff) = *(const float4*)(XL + c * PW + w4);
    *(float4*)(out_h + goff) = *(const float4*)(XH + c * PW + w4);
  }
}

}  // namespace

extern "C" void kernel_launch(void* const* d_in, const int* in_sizes, int n_in,
                              void* d_out, int out_size) {
  const float* x_l = (const float*)d_in[0];
  const float* x_h = (const float*)d_in[1];
  const float* g1 = (const float*)d_in[2];
  const float* b1 = (const float*)d_in[3];
  const float* g2 = (const float*)d_in[4];
  const float* b2 = (const float*)d_in[5];
  const float* Wq = (const float*)d_in[6];
  const float* Wk = (const float*)d_in[7];
  const float* Wv1 = (const float*)d_in[8];
  const float* Wv2 = (const float*)d_in[9];

  float* out = (float*)d_out;
  float* out_l = out;
  float* out_h = out + (size_t)kB * kC * kH * kW;

  const size_t smem = (size_t)SMEM_FLOATS * sizeof(float);  // ~219 KB
  cudaFuncSetAttribute(scam_kernel, cudaFuncAttributeMaxDynamicSharedMemorySize, (int)smem);
  scam_kernel<<<kB * kH, NTHR, smem>>>(x_l, x_h, g1, b1, g2, b2, Wq, Wk, Wv1, Wv2,
                                       out_l, out_h);
}